// round 1
// baseline (speedup 1.0000x reference)
#include <cuda_runtime.h>
#include <cuda_bf16.h>

#define DIMC   768
#define NHEAD  12
#define HDIM   64
#define NBATCH 8
#define NTOK   1024                 // 32*32 tokens per batch
#define MTOK   (NBATCH * NTOK)      // 8192 total rows

// Scratch (allocation-free): qkv = [8192, 2304], attn out = [8192, 768]
__device__ float g_qkv[(size_t)MTOK * 3 * DIMC];
__device__ float g_attn[(size_t)MTOK * DIMC];

// ---------------------------------------------------------------------------
// Tiled fp32 SGEMM: C[M,N] = A[M,K] @ B[K,N] (+ bias). 128x128x16, 8x8 microtile.
// M % 128 == 0, N % 128 == 0, K % 16 == 0 (holds for all our shapes).
// ---------------------------------------------------------------------------
template<bool BIAS>
__global__ void __launch_bounds__(256) sgemm128(
    const float* __restrict__ A, const float* __restrict__ B,
    const float* __restrict__ bias, float* __restrict__ C,
    int M, int N, int K)
{
    __shared__ float As[16][128];   // stored transposed: As[k][m]
    __shared__ float Bs[16][128];   // Bs[k][n]

    const int t  = threadIdx.x;
    const int bm = blockIdx.y * 128;
    const int bn = blockIdx.x * 128;
    const int tx = (t & 15) * 8;    // col offset of 8x8 microtile
    const int ty = (t >> 4) * 8;    // row offset

    float acc[8][8];
    #pragma unroll
    for (int i = 0; i < 8; i++)
        #pragma unroll
        for (int j = 0; j < 8; j++) acc[i][j] = 0.f;

    for (int k0 = 0; k0 < K; k0 += 16) {
        // Load A tile (128x16) as 512 float4, 2 per thread, transpose into As
        #pragma unroll
        for (int i = 0; i < 2; i++) {
            int v   = t + 256 * i;
            int row = v >> 2;
            int kc  = (v & 3) * 4;
            float4 a4 = *(const float4*)(A + (size_t)(bm + row) * K + k0 + kc);
            As[kc + 0][row] = a4.x;
            As[kc + 1][row] = a4.y;
            As[kc + 2][row] = a4.z;
            As[kc + 3][row] = a4.w;
        }
        // Load B tile (16x128) as 512 float4, 2 per thread
        #pragma unroll
        for (int i = 0; i < 2; i++) {
            int v   = t + 256 * i;
            int row = v >> 5;
            int col = (v & 31) * 4;
            *(float4*)&Bs[row][col] =
                *(const float4*)(B + (size_t)(k0 + row) * N + bn + col);
        }
        __syncthreads();

        #pragma unroll
        for (int kk = 0; kk < 16; kk++) {
            float ar[8], br[8];
            *(float4*)&ar[0] = *(float4*)&As[kk][ty];
            *(float4*)&ar[4] = *(float4*)&As[kk][ty + 4];
            *(float4*)&br[0] = *(float4*)&Bs[kk][tx];
            *(float4*)&br[4] = *(float4*)&Bs[kk][tx + 4];
            #pragma unroll
            for (int i = 0; i < 8; i++)
                #pragma unroll
                for (int j = 0; j < 8; j++)
                    acc[i][j] = fmaf(ar[i], br[j], acc[i][j]);
        }
        __syncthreads();
    }

    #pragma unroll
    for (int i = 0; i < 8; i++) {
        #pragma unroll
        for (int j = 0; j < 8; j += 4) {
            float4 o;
            o.x = acc[i][j + 0];
            o.y = acc[i][j + 1];
            o.z = acc[i][j + 2];
            o.w = acc[i][j + 3];
            if (BIAS) {
                o.x += bias[bn + tx + j + 0];
                o.y += bias[bn + tx + j + 1];
                o.z += bias[bn + tx + j + 2];
                o.w += bias[bn + tx + j + 3];
            }
            *(float4*)(C + (size_t)(bm + ty + i) * N + bn + tx + j) = o;
        }
    }
}

// ---------------------------------------------------------------------------
// Flash attention, fp32. One thread per query row (blockDim = 64 = BM).
// qkv layout per token row (stride 2304): [q(12*64) | k(12*64) | v(12*64)].
// Online softmax in 16-key chunks; Q/acc/scores in registers; K/V tiles in smem
// read as broadcast float4.
// Writes attn output as [MTOK, 768] with channel = h*64+d.
// ---------------------------------------------------------------------------
__global__ void __launch_bounds__(64) attn_kernel(
    const float* __restrict__ qkv, float* __restrict__ out)
{
    __shared__ float Ks[64][64];
    __shared__ float Vs[64][64];

    const int t  = threadIdx.x;           // query row within tile
    const int qt = blockIdx.x;            // query tile (0..15)
    const int bh = blockIdx.y;            // 0..95
    const int b  = bh / NHEAD;
    const int h  = bh - b * NHEAD;
    const int row = qt * 64 + t;

    const float* qptr = qkv + (size_t)(b * NTOK + row) * (3 * DIMC) + h * HDIM;
    float q[64];
    #pragma unroll
    for (int i = 0; i < 16; i++) {
        float4 v = *(const float4*)(qptr + 4 * i);
        q[4 * i + 0] = v.x * 0.125f;   // SCALE = 64^-0.5
        q[4 * i + 1] = v.y * 0.125f;
        q[4 * i + 2] = v.z * 0.125f;
        q[4 * i + 3] = v.w * 0.125f;
    }

    float m = -1e30f, l = 0.f;
    float acc[64];
    #pragma unroll
    for (int i = 0; i < 64; i++) acc[i] = 0.f;

    const int rr = t >> 4;            // 0..3 (row group for coop loads)
    const int cc = (t & 15) * 4;      // 0..60 (col offset)

    for (int kt = 0; kt < 16; kt++) {
        __syncthreads();
        const float* kbase =
            qkv + (size_t)(b * NTOK + kt * 64) * (3 * DIMC) + DIMC + h * HDIM;
        #pragma unroll
        for (int s = 0; s < 16; s++) {
            int r2 = s * 4 + rr;
            const float* rp = kbase + (size_t)r2 * (3 * DIMC);
            *(float4*)&Ks[r2][cc] = *(const float4*)(rp + cc);           // K
            *(float4*)&Vs[r2][cc] = *(const float4*)(rp + DIMC + cc);    // V
        }
        __syncthreads();

        #pragma unroll 1
        for (int c = 0; c < 4; c++) {          // 16-key chunks
            float sc[16];
            #pragma unroll
            for (int jj = 0; jj < 16; jj++) {
                int j = c * 16 + jj;
                float sv = 0.f;
                #pragma unroll
                for (int d4 = 0; d4 < 16; d4++) {
                    float4 kv = *(float4*)&Ks[j][d4 * 4];
                    sv = fmaf(q[d4 * 4 + 0], kv.x, sv);
                    sv = fmaf(q[d4 * 4 + 1], kv.y, sv);
                    sv = fmaf(q[d4 * 4 + 2], kv.z, sv);
                    sv = fmaf(q[d4 * 4 + 3], kv.w, sv);
                }
                sc[jj] = sv;
            }
            float mx = m;
            #pragma unroll
            for (int jj = 0; jj < 16; jj++) mx = fmaxf(mx, sc[jj]);
            if (mx > m) {
                float rs = __expf(m - mx);
                l *= rs;
                #pragma unroll
                for (int i = 0; i < 64; i++) acc[i] *= rs;
                m = mx;
            }
            #pragma unroll
            for (int jj = 0; jj < 16; jj++) {
                float p = __expf(sc[jj] - m);
                l += p;
                int j = c * 16 + jj;
                #pragma unroll
                for (int d4 = 0; d4 < 16; d4++) {
                    float4 vv = *(float4*)&Vs[j][d4 * 4];
                    acc[d4 * 4 + 0] = fmaf(p, vv.x, acc[d4 * 4 + 0]);
                    acc[d4 * 4 + 1] = fmaf(p, vv.y, acc[d4 * 4 + 1]);
                    acc[d4 * 4 + 2] = fmaf(p, vv.z, acc[d4 * 4 + 2]);
                    acc[d4 * 4 + 3] = fmaf(p, vv.w, acc[d4 * 4 + 3]);
                }
            }
        }
    }

    float inv = 1.0f / l;
    float* op = out + (size_t)(b * NTOK + row) * DIMC + h * HDIM;
    #pragma unroll
    for (int i = 0; i < 16; i++) {
        float4 o;
        o.x = acc[4 * i + 0] * inv;
        o.y = acc[4 * i + 1] * inv;
        o.z = acc[4 * i + 2] * inv;
        o.w = acc[4 * i + 3] * inv;
        *(float4*)(op + 4 * i) = o;
    }
}

// ---------------------------------------------------------------------------
// kernel_launch: 3 launches, graph-capturable, allocation-free.
// Inputs (metadata order): x[8,32,32,768], w_qkv[768,2304], w_proj[768,768], b_proj[768]
// ---------------------------------------------------------------------------
extern "C" void kernel_launch(void* const* d_in, const int* in_sizes, int n_in,
                              void* d_out, int out_size)
{
    const float* x      = (const float*)d_in[0];
    const float* w_qkv  = (const float*)d_in[1];
    const float* w_proj = (const float*)d_in[2];
    const float* b_proj = (const float*)d_in[3];
    float*       out    = (float*)d_out;

    void *qkv_p = nullptr, *attn_p = nullptr;
    cudaGetSymbolAddress(&qkv_p, g_qkv);
    cudaGetSymbolAddress(&attn_p, g_attn);

    // 1) QKV GEMM: [8192,768] @ [768,2304]
    sgemm128<false><<<dim3((3 * DIMC) / 128, MTOK / 128), 256>>>(
        x, w_qkv, nullptr, (float*)qkv_p, MTOK, 3 * DIMC, DIMC);

    // 2) Attention: (16 q-tiles) x (96 batch-heads)
    attn_kernel<<<dim3(NTOK / 64, NBATCH * NHEAD), 64>>>(
        (const float*)qkv_p, (float*)attn_p);

    // 3) Output projection + bias: [8192,768] @ [768,768]
    sgemm128<true><<<dim3(DIMC / 128, MTOK / 128), 256>>>(
        (const float*)attn_p, w_proj, b_proj, out, MTOK, DIMC, DIMC);
}

// round 2
// speedup vs baseline: 3.7201x; 3.7201x over previous
#include <cuda_runtime.h>
#include <cuda_bf16.h>
#include <cstdint>

#define DIMC   768
#define NHEAD  12
#define HDIM   64
#define NBATCH 8
#define NTOK   1024
#define MTOK   (NBATCH * NTOK)

// Scratch (allocation-free)
__device__ float g_qkv[(size_t)MTOK * 3 * DIMC];
__device__ float g_attn[(size_t)MTOK * DIMC];

// ---------------------------------------------------------------------------
// helpers
// ---------------------------------------------------------------------------
__device__ __forceinline__ unsigned f2tf(float x) {
    unsigned r;
    asm("cvt.rna.tf32.f32 %0, %1;" : "=r"(r) : "f"(x));
    return r;
}

// D += A @ B  (m16n8k8, tf32 inputs, f32 accumulate)
__device__ __forceinline__ void mma8(float* d, const unsigned* a, const unsigned* b) {
    asm volatile(
        "mma.sync.aligned.m16n8k8.row.col.f32.tf32.tf32.f32 "
        "{%0,%1,%2,%3},{%4,%5,%6,%7},{%8,%9},{%0,%1,%2,%3};\n"
        : "+f"(d[0]), "+f"(d[1]), "+f"(d[2]), "+f"(d[3])
        : "r"(a[0]), "r"(a[1]), "r"(a[2]), "r"(a[3]),
          "r"(b[0]), "r"(b[1]));
}

// ---------------------------------------------------------------------------
// tf32 tensor-core GEMM: C[M,N] = A[M,K] @ B[K,N] (+bias).
// 128x128x32 block tile, 256 threads = 8 warps (4x2), warp tile 32x64.
// All fragment LDS are bank-conflict-free (As stride 36, Bs stride 136).
// ---------------------------------------------------------------------------
template<bool BIAS>
__global__ void __launch_bounds__(256) mm_tf32(
    const float* __restrict__ A, const float* __restrict__ B,
    const float* __restrict__ bias, float* __restrict__ C,
    int M, int N, int K)
{
    __shared__ unsigned As[128][36];   // m-major: As[m][k], stride 36
    __shared__ unsigned Bs[32][136];   // k-major: Bs[k][n], stride 136

    const int t    = threadIdx.x;
    const int lane = t & 31;
    const int warp = t >> 5;
    const int wm   = warp >> 1;        // 0..3
    const int wn   = warp & 1;         // 0..1
    const int g    = lane >> 2;        // 0..7
    const int tg   = lane & 3;         // 0..3
    const int bm   = blockIdx.y * 128;
    const int bn   = blockIdx.x * 128;

    float acc[2][8][4];
    #pragma unroll
    for (int mt = 0; mt < 2; mt++)
        #pragma unroll
        for (int nt = 0; nt < 8; nt++)
            #pragma unroll
            for (int i = 0; i < 4; i++) acc[mt][nt][i] = 0.f;

    for (int k0 = 0; k0 < K; k0 += 32) {
        // A tile 128x32 -> As[m][k] (convert to tf32 on store)
        #pragma unroll
        for (int i = 0; i < 4; i++) {
            int v = t + 256 * i;
            int r = v >> 3, c = (v & 7) * 4;
            float4 a4 = *(const float4*)(A + (size_t)(bm + r) * K + k0 + c);
            uint4 u;
            u.x = f2tf(a4.x); u.y = f2tf(a4.y); u.z = f2tf(a4.z); u.w = f2tf(a4.w);
            *(uint4*)&As[r][c] = u;
        }
        // B tile 32x128 -> Bs[k][n]
        #pragma unroll
        for (int i = 0; i < 4; i++) {
            int v = t + 256 * i;
            int r = v >> 5, c = (v & 31) * 4;
            float4 b4 = *(const float4*)(B + (size_t)(k0 + r) * N + bn + c);
            uint4 u;
            u.x = f2tf(b4.x); u.y = f2tf(b4.y); u.z = f2tf(b4.z); u.w = f2tf(b4.w);
            *(uint4*)&Bs[r][c] = u;
        }
        __syncthreads();

        #pragma unroll
        for (int ks = 0; ks < 4; ks++) {
            unsigned af[2][4], bf[8][2];
            #pragma unroll
            for (int mt = 0; mt < 2; mt++) {
                int r = wm * 32 + mt * 16 + g;
                int c = ks * 8 + tg;
                af[mt][0] = As[r][c];
                af[mt][1] = As[r + 8][c];
                af[mt][2] = As[r][c + 4];
                af[mt][3] = As[r + 8][c + 4];
            }
            #pragma unroll
            for (int nt = 0; nt < 8; nt++) {
                int cc = wn * 64 + nt * 8 + g;
                int r  = ks * 8 + tg;
                bf[nt][0] = Bs[r][cc];
                bf[nt][1] = Bs[r + 4][cc];
            }
            #pragma unroll
            for (int mt = 0; mt < 2; mt++)
                #pragma unroll
                for (int nt = 0; nt < 8; nt++)
                    mma8(acc[mt][nt], af[mt], bf[nt]);
        }
        __syncthreads();
    }

    #pragma unroll
    for (int mt = 0; mt < 2; mt++) {
        int r0 = bm + wm * 32 + mt * 16 + g;
        #pragma unroll
        for (int nt = 0; nt < 8; nt++) {
            int cc = bn + wn * 64 + nt * 8 + tg * 2;
            float2 v0 = make_float2(acc[mt][nt][0], acc[mt][nt][1]);
            float2 v1 = make_float2(acc[mt][nt][2], acc[mt][nt][3]);
            if (BIAS) {
                float2 bb = *(const float2*)(bias + cc);
                v0.x += bb.x; v0.y += bb.y;
                v1.x += bb.x; v1.y += bb.y;
            }
            *(float2*)(C + (size_t)r0 * N + cc)       = v0;
            *(float2*)(C + (size_t)(r0 + 8) * N + cc) = v1;
        }
    }
}

// ---------------------------------------------------------------------------
// Flash attention with tf32 mma. Block = 128 threads (4 warps), each warp owns
// 16 query rows. BM=64 q rows per block, BN=64 keys per iteration, d=64.
// S = Q@K^T via mma; online softmax in fragments; P converted C-layout ->
// A-layout via shuffles; O += P@V via mma.
// ---------------------------------------------------------------------------
__global__ void __launch_bounds__(128) attn_tf32(
    const float* __restrict__ qkv, float* __restrict__ out)
{
    __shared__ unsigned Ks[64][68];   // K tile [key][d], also Q staging
    __shared__ unsigned Vs[64][72];   // V tile [key][d]

    const int t    = threadIdx.x;
    const int lane = t & 31;
    const int warp = t >> 5;
    const int g    = lane >> 2;
    const int tg   = lane & 3;
    const int qt   = blockIdx.x;      // 0..15
    const int bh   = blockIdx.y;      // 0..95
    const int b    = bh / NHEAD;
    const int h    = bh - b * NHEAD;
    const size_t rs = 3 * DIMC;

    // ---- stage Q (scaled) through Ks, pull A-fragments into registers ----
    const float* qbase = qkv + (size_t)(b * NTOK + qt * 64) * rs + h * HDIM;
    #pragma unroll
    for (int i = 0; i < 8; i++) {
        int v = t + 128 * i;
        int r = v >> 4, c = (v & 15) * 4;
        float4 q4 = *(const float4*)(qbase + (size_t)r * rs + c);
        uint4 u;
        u.x = f2tf(q4.x * 0.125f); u.y = f2tf(q4.y * 0.125f);
        u.z = f2tf(q4.z * 0.125f); u.w = f2tf(q4.w * 0.125f);
        *(uint4*)&Ks[r][c] = u;
    }
    __syncthreads();

    unsigned qa[8][4];
    {
        int r = warp * 16 + g;
        #pragma unroll
        for (int ks = 0; ks < 8; ks++) {
            int c = ks * 8 + tg;
            qa[ks][0] = Ks[r][c];
            qa[ks][1] = Ks[r + 8][c];
            qa[ks][2] = Ks[r][c + 4];
            qa[ks][3] = Ks[r + 8][c + 4];
        }
    }
    __syncthreads();

    float oacc[8][4];
    #pragma unroll
    for (int dt = 0; dt < 8; dt++)
        #pragma unroll
        for (int i = 0; i < 4; i++) oacc[dt][i] = 0.f;

    float m0 = -1e30f, m1 = -1e30f, l0 = 0.f, l1 = 0.f;

    const float* kvb = qkv + (size_t)(b * NTOK) * rs + DIMC + h * HDIM;

    for (int kt = 0; kt < 16; kt++) {
        // ---- load K, V tiles (64 keys x 64 d), convert to tf32 ----
        const float* kb = kvb + (size_t)(kt * 64) * rs;
        #pragma unroll
        for (int i = 0; i < 8; i++) {
            int v = t + 128 * i;
            int r = v >> 4, c = (v & 15) * 4;
            const float* rp = kb + (size_t)r * rs;
            float4 k4 = *(const float4*)(rp + c);
            float4 v4 = *(const float4*)(rp + DIMC + c);
            uint4 uk, uv;
            uk.x = f2tf(k4.x); uk.y = f2tf(k4.y); uk.z = f2tf(k4.z); uk.w = f2tf(k4.w);
            uv.x = f2tf(v4.x); uv.y = f2tf(v4.y); uv.z = f2tf(v4.z); uv.w = f2tf(v4.w);
            *(uint4*)&Ks[r][c] = uk;
            *(uint4*)&Vs[r][c] = uv;
        }
        __syncthreads();

        // ---- S = Q @ K^T : warp computes 16 rows x 64 keys ----
        float sacc[8][4];
        #pragma unroll
        for (int nt = 0; nt < 8; nt++)
            #pragma unroll
            for (int i = 0; i < 4; i++) sacc[nt][i] = 0.f;

        #pragma unroll
        for (int ks = 0; ks < 8; ks++) {
            int d = ks * 8 + tg;
            #pragma unroll
            for (int nt = 0; nt < 8; nt++) {
                unsigned bf[2];
                int key = nt * 8 + g;
                bf[0] = Ks[key][d];
                bf[1] = Ks[key][d + 4];
                mma8(sacc[nt], qa[ks], bf);
            }
        }

        // ---- online softmax over fragments ----
        float mx0 = -1e30f, mx1 = -1e30f;
        #pragma unroll
        for (int nt = 0; nt < 8; nt++) {
            mx0 = fmaxf(mx0, fmaxf(sacc[nt][0], sacc[nt][1]));
            mx1 = fmaxf(mx1, fmaxf(sacc[nt][2], sacc[nt][3]));
        }
        mx0 = fmaxf(mx0, __shfl_xor_sync(0xFFFFFFFFu, mx0, 1));
        mx0 = fmaxf(mx0, __shfl_xor_sync(0xFFFFFFFFu, mx0, 2));
        mx1 = fmaxf(mx1, __shfl_xor_sync(0xFFFFFFFFu, mx1, 1));
        mx1 = fmaxf(mx1, __shfl_xor_sync(0xFFFFFFFFu, mx1, 2));

        float nm0 = fmaxf(m0, mx0), nm1 = fmaxf(m1, mx1);
        float a0 = __expf(m0 - nm0), a1 = __expf(m1 - nm1);
        m0 = nm0; m1 = nm1;

        float s0 = 0.f, s1 = 0.f;
        unsigned pf[8][4];
        #pragma unroll
        for (int nt = 0; nt < 8; nt++) {
            float p0 = __expf(sacc[nt][0] - m0);
            float p1 = __expf(sacc[nt][1] - m0);
            float p2 = __expf(sacc[nt][2] - m1);
            float p3 = __expf(sacc[nt][3] - m1);
            s0 += p0 + p1;
            s1 += p2 + p3;
            pf[nt][0] = f2tf(p0); pf[nt][1] = f2tf(p1);
            pf[nt][2] = f2tf(p2); pf[nt][3] = f2tf(p3);
            oacc[nt][0] *= a0; oacc[nt][1] *= a0;
            oacc[nt][2] *= a1; oacc[nt][3] *= a1;
        }
        s0 += __shfl_xor_sync(0xFFFFFFFFu, s0, 1);
        s0 += __shfl_xor_sync(0xFFFFFFFFu, s0, 2);
        s1 += __shfl_xor_sync(0xFFFFFFFFu, s1, 1);
        s1 += __shfl_xor_sync(0xFFFFFFFFu, s1, 2);
        l0 = l0 * a0 + s0;
        l1 = l1 * a1 + s1;

        // ---- O += P @ V : P C-layout -> A-layout via shuffles ----
        const int src0 = (lane & ~3) | (tg >> 1);
        const int src2 = src0 + 2;
        #pragma unroll
        for (int ks = 0; ks < 8; ks++) {
            unsigned x0 = __shfl_sync(0xFFFFFFFFu, pf[ks][0], src0);
            unsigned x1 = __shfl_sync(0xFFFFFFFFu, pf[ks][1], src0);
            unsigned x2 = __shfl_sync(0xFFFFFFFFu, pf[ks][2], src0);
            unsigned x3 = __shfl_sync(0xFFFFFFFFu, pf[ks][3], src0);
            unsigned y0 = __shfl_sync(0xFFFFFFFFu, pf[ks][0], src2);
            unsigned y1 = __shfl_sync(0xFFFFFFFFu, pf[ks][1], src2);
            unsigned y2 = __shfl_sync(0xFFFFFFFFu, pf[ks][2], src2);
            unsigned y3 = __shfl_sync(0xFFFFFFFFu, pf[ks][3], src2);
            unsigned pa[4];
            pa[0] = (tg & 1) ? x1 : x0;   // (row,  key=tg)
            pa[1] = (tg & 1) ? x3 : x2;   // (row+8,key=tg)
            pa[2] = (tg & 1) ? y1 : y0;   // (row,  key=tg+4)
            pa[3] = (tg & 1) ? y3 : y2;   // (row+8,key=tg+4)

            int key = ks * 8 + tg;
            #pragma unroll
            for (int dt = 0; dt < 8; dt++) {
                unsigned vb[2];
                int d = dt * 8 + g;
                vb[0] = Vs[key][d];
                vb[1] = Vs[key + 4][d];
                mma8(oacc[dt], pa, vb);
            }
        }
        __syncthreads();
    }

    // ---- epilogue: normalize and store ----
    float inv0 = 1.0f / l0, inv1 = 1.0f / l1;
    int token = b * NTOK + qt * 64 + warp * 16 + g;
    float* op = out + (size_t)token * DIMC + h * HDIM;
    #pragma unroll
    for (int dt = 0; dt < 8; dt++) {
        int d = dt * 8 + tg * 2;
        float2 v0 = make_float2(oacc[dt][0] * inv0, oacc[dt][1] * inv0);
        float2 v1 = make_float2(oacc[dt][2] * inv1, oacc[dt][3] * inv1);
        *(float2*)(op + d)            = v0;
        *(float2*)(op + 8 * DIMC + d) = v1;
    }
}

// ---------------------------------------------------------------------------
// kernel_launch
// ---------------------------------------------------------------------------
extern "C" void kernel_launch(void* const* d_in, const int* in_sizes, int n_in,
                              void* d_out, int out_size)
{
    const float* x      = (const float*)d_in[0];
    const float* w_qkv  = (const float*)d_in[1];
    const float* w_proj = (const float*)d_in[2];
    const float* b_proj = (const float*)d_in[3];
    float*       out    = (float*)d_out;

    void *qkv_p = nullptr, *attn_p = nullptr;
    cudaGetSymbolAddress(&qkv_p, g_qkv);
    cudaGetSymbolAddress(&attn_p, g_attn);

    // 1) QKV GEMM: [8192,768] @ [768,2304]
    mm_tf32<false><<<dim3((3 * DIMC) / 128, MTOK / 128), 256>>>(
        x, w_qkv, nullptr, (float*)qkv_p, MTOK, 3 * DIMC, DIMC);

    // 2) Attention
    attn_tf32<<<dim3(NTOK / 64, NBATCH * NHEAD), 128>>>(
        (const float*)qkv_p, (float*)attn_p);

    // 3) Projection + bias: [8192,768] @ [768,768]
    mm_tf32<true><<<dim3(DIMC / 128, MTOK / 128), 256>>>(
        (const float*)attn_p, w_proj, b_proj, out, MTOK, DIMC, DIMC);
}